// round 12
// baseline (speedup 1.0000x reference)
#include <cuda_runtime.h>
#include <cuda_fp16.h>
#include <cstdint>

// GCN layer on GB300, round-12: CSR build collapsed into ONE persistent
// kernel with software grid barriers (detect+zero -> degree -> decoupled-
// lookback scan -> fill). A-chain: csr -> aggregate -> fused GEMM1+2.
// Stream B (forked): nh->fp16, eh passthrough.

#define NN 100000
#define EE 1600000
#define DD 128
#define MTILES 6250        // 100000/16
#define NBLK 391           // ceil(NN/256); all co-resident (<=444 slots)
#define NT (NBLK * 256)    // 100096 threads in csr kernel
#define WSTRIDE 136
#define SMEM_GEMM (2 * DD * WSTRIDE * (int)sizeof(__half))   // 69,632B

__device__ __align__(128) int     g_cnt[NN];
__device__ __align__(128) int     g_off[NN];
__device__ __align__(128) int     g_cur[NN];
__device__ __align__(128) unsigned long long g_comb[NBLK];  // scan state
__device__ __align__(128) int     g_esrc[EE];
__device__ __align__(128) float   g_dis[NN];
__device__ __align__(128) __half2 g_nhh[(size_t)NN * 64];  // nh fp16
__device__ __align__(128) __half2 g_xh [(size_t)NN * 64];  // agg fp16
__device__ unsigned g_odd_or;       // 0 => edge_index is int64
__device__ unsigned g_barcnt[4];    // grid barrier counters (self-resetting)
__device__ unsigned g_barrel[4];    // grid barrier generations

// ---------- helpers ----------
__device__ __forceinline__ int edge_idx(const void* ei, int table, int e, bool is64) {
    if (is64) return (int)((const long long*)ei)[(size_t)table * EE + e];
    return ((const int*)ei)[(size_t)table * EE + e];
}
__device__ __forceinline__ uint32_t h2bits(__half2 h) {
    return *reinterpret_cast<uint32_t*>(&h);
}
__device__ __forceinline__ uint32_t packh2(float a, float b) {
    __half2 h = __floats2half2_rn(a, b);
    return *reinterpret_cast<uint32_t*>(&h);
}
__device__ __forceinline__ void mma16816(float c[4], const uint32_t a[4],
                                         uint32_t b0, uint32_t b1) {
    asm volatile(
        "mma.sync.aligned.m16n8k16.row.col.f32.f16.f16.f32 "
        "{%0,%1,%2,%3}, {%4,%5,%6,%7}, {%8,%9}, {%0,%1,%2,%3};"
        : "+f"(c[0]), "+f"(c[1]), "+f"(c[2]), "+f"(c[3])
        : "r"(a[0]), "r"(a[1]), "r"(a[2]), "r"(a[3]), "r"(b0), "r"(b1));
}

// Grid barrier: gen read BEFORE arrive is race-free (release requires my
// own arrival). Counter self-resets; generation survives graph replays.
__device__ __forceinline__ void grid_bar(int slot) {
    __syncthreads();
    if (threadIdx.x == 0) {
        __threadfence();
        unsigned gen = atomicAdd(&g_barrel[slot], 0u);
        unsigned arr = atomicAdd(&g_barcnt[slot], 1u);
        if (arr == NBLK - 1) {
            atomicExch(&g_barcnt[slot], 0u);
            atomicAdd(&g_barrel[slot], 1u);
        } else {
            while (atomicAdd(&g_barrel[slot], 0u) == gen) {}
        }
        __threadfence();
    }
    __syncthreads();
}

// ---------- persistent CSR kernel: detect+zero -> degree -> scan -> fill ----
__global__ void __launch_bounds__(256, 4) csr_kernel(const void* __restrict__ ei) {
    const int tid = threadIdx.x, b = blockIdx.x;
    const int gt = b * 256 + tid;

    // phase 0: zero counters + scan state; block 0 detects index dtype
    if (gt < NN) g_cnt[gt] = 0;
    if (gt < NBLK) g_comb[gt] = 0ull;
    if (b == 0) {
        __shared__ unsigned sred[256];
        const unsigned* w = (const unsigned*)ei;
        unsigned v = 0;
        #pragma unroll
        for (int j = 0; j < 16; ++j) v |= w[2 * (tid + 256 * j) + 1];
        sred[tid] = v;
        __syncthreads();
        #pragma unroll
        for (int o = 128; o > 0; o >>= 1) {
            if (tid < o) sred[tid] |= sred[tid + o];
            __syncthreads();
        }
        if (tid == 0) g_odd_or = sred[0];
    }
    grid_bar(0);

    // phase 1: degree histogram (grid-stride over edges)
    const bool is64 = (g_odd_or == 0u);
    for (int e = gt; e < EE; e += NT) {
        unsigned dst = (unsigned)edge_idx(ei, 1, e, is64);
        if (dst < NN) atomicAdd(&g_cnt[dst], 1);
    }
    grid_bar(1);

    // phase 2: decoupled-lookback exclusive scan + cursors + dis.
    // g_cnt read via __ldcg (atomically-updated lines may be stale in L1).
    {
        __shared__ int s[256];
        __shared__ int sprefix;
        int i = gt;
        int v = (i < NN) ? __ldcg(&g_cnt[i]) : 0;
        s[tid] = v;
        __syncthreads();
        #pragma unroll
        for (int o = 1; o < 256; o <<= 1) {
            int x = (tid >= o) ? s[tid - o] : 0;
            __syncthreads();
            s[tid] += x;
            __syncthreads();
        }
        int agg = s[255];
        if (tid == 0) {
            if (b == 0) {
                sprefix = 0;
                atomicExch(&g_comb[0], (2ull << 32) | (unsigned)agg);
            } else {
                atomicExch(&g_comb[b], (1ull << 32) | (unsigned)agg);
            }
        }
        if (b > 0 && tid < 32) {
            const int lane = tid;
            int prefix = 0;
            int base = b - 1;
            while (true) {
                int idx = base - lane;
                unsigned long long c;
                unsigned st;
                do {
                    c = (idx >= 0) ? atomicAdd(&g_comb[idx], 0ull) : (2ull << 32);
                    st = (unsigned)(c >> 32);
                } while (__any_sync(0xffffffffu, st == 0));
                int val = (int)(c & 0xffffffffu);
                unsigned m2 = __ballot_sync(0xffffffffu, st == 2);
                if (m2) {
                    int firstp = __ffs(m2) - 1;
                    int contrib = (lane <= firstp) ? val : 0;
                    prefix += __reduce_add_sync(0xffffffffu, contrib);
                    break;
                }
                prefix += __reduce_add_sync(0xffffffffu, val);
                base -= 32;
            }
            if (lane == 0) {
                atomicExch(&g_comb[b], (2ull << 32) | (unsigned)(prefix + agg));
                sprefix = prefix;
            }
        }
        __syncthreads();
        if (i < NN) {
            int excl = sprefix + s[tid] - v;
            g_off[i] = excl;
            g_cur[i] = excl;
            g_dis[i] = (v > 0) ? rsqrtf((float)v) : 0.f;
        }
    }
    grid_bar(2);

    // phase 3: bucket fill (edge_index now L2-warm from phase 1)
    for (int e = gt; e < EE; e += NT) {
        int src = edge_idx(ei, 0, e, is64);
        int dst = edge_idx(ei, 1, e, is64);
        if ((unsigned)src >= NN || (unsigned)dst >= NN) continue;
        int pos = atomicAdd(&g_cur[dst], 1);
        g_esrc[pos] = src;
    }
}

// ---------- nh -> fp16 (stream B) ----------
__global__ void nh2h_kernel(const float* __restrict__ nh) {
    int idx = blockIdx.x * blockDim.x + threadIdx.x;
    if (idx < NN * 32) {
        float4 v = __ldg(reinterpret_cast<const float4*>(nh) + idx);
        g_nhh[2 * idx]     = __floats2half2_rn(v.x, v.y);
        g_nhh[2 * idx + 1] = __floats2half2_rn(v.z, v.w);
    }
}

// ---------- aggregate: warp per destination node (fp16 gather) ----------
__global__ void aggregate_kernel() {
    int w = (blockIdx.x * blockDim.x + threadIdx.x) >> 5;
    int lane = threadIdx.x & 31;
    if (w >= NN) return;
    int off = g_off[w], len = g_cnt[w];
    float4 acc = make_float4(0.f, 0.f, 0.f, 0.f);
    for (int b = 0; b < len; b += 32) {
        int n = min(32, len - b);
        int src = (lane < n) ? __ldg(&g_esrc[off + b + lane]) : 0;
        float s  = (lane < n) ? __ldg(&g_dis[src]) : 0.f;
        for (int i = 0; i < n; ++i) {
            int   ss = __shfl_sync(0xffffffffu, src, i);
            float sv = __shfl_sync(0xffffffffu, s, i);
            float2 raw = __ldg(reinterpret_cast<const float2*>(g_nhh)
                               + (size_t)ss * 32 + lane);
            __half2 h0 = *reinterpret_cast<__half2*>(&raw.x);
            __half2 h1 = *reinterpret_cast<__half2*>(&raw.y);
            float2 f0 = __half22float2(h0), f1 = __half22float2(h1);
            acc.x += f0.x * sv; acc.y += f0.y * sv;
            acc.z += f1.x * sv; acc.w += f1.y * sv;
        }
    }
    float dd = g_dis[w];
    g_xh[(size_t)w * 64 + lane * 2]     = __floats2half2_rn(acc.x * dd, acc.y * dd);
    g_xh[(size_t)w * 64 + lane * 2 + 1] = __floats2half2_rn(acc.z * dd, acc.w * dd);
}

// ---------- fused GEMM1+GEMM2, register-chained HMMA ----------
__global__ void __launch_bounds__(256) gemm12_kernel(
    const float* __restrict__ W1, const float* __restrict__ b1,
    const float* __restrict__ W2, const float* __restrict__ b2,
    float* __restrict__ out) {
    extern __shared__ __half sW[];
    __half* sW1 = sW;
    __half* sW2 = sW + DD * WSTRIDE;
    const int tid = threadIdx.x, lane = tid & 31, warp = tid >> 5;
    const int gid = lane >> 2, tq = lane & 3;

    for (int idx = tid; idx < DD * DD; idx += 256) {
        int k = idx >> 7, n = idx & 127;
        sW1[n * WSTRIDE + k] = __float2half(W1[idx]);
        sW2[n * WSTRIDE + k] = __float2half(W2[idx]);
    }
    __syncthreads();

    for (int mt = blockIdx.x * 8 + warp; mt < MTILES; mt += gridDim.x * 8) {
        const __half2* X0 = g_xh + (size_t)(mt * 16 + gid) * 64;
        const __half2* X1 = X0 + 8 * 64;

        float acc1[16][4];
        #pragma unroll
        for (int t = 0; t < 16; ++t)
            acc1[t][0] = acc1[t][1] = acc1[t][2] = acc1[t][3] = 0.f;
        #pragma unroll
        for (int kc = 0; kc < 8; ++kc) {
            uint32_t a[4];
            a[0] = h2bits(__ldg(X0 + kc * 8 + tq));
            a[1] = h2bits(__ldg(X1 + kc * 8 + tq));
            a[2] = h2bits(__ldg(X0 + kc * 8 + 4 + tq));
            a[3] = h2bits(__ldg(X1 + kc * 8 + 4 + tq));
            #pragma unroll
            for (int t = 0; t < 16; ++t) {
                int n = 8 * t + gid;
                uint32_t b0 = h2bits(*reinterpret_cast<const __half2*>(
                    &sW1[n * WSTRIDE + kc * 16 + 2 * tq]));
                uint32_t b1v = h2bits(*reinterpret_cast<const __half2*>(
                    &sW1[n * WSTRIDE + kc * 16 + 8 + 2 * tq]));
                mma16816(acc1[t], a, b0, b1v);
            }
        }

        float acc2[16][4];
        #pragma unroll
        for (int t = 0; t < 16; ++t)
            acc2[t][0] = acc2[t][1] = acc2[t][2] = acc2[t][3] = 0.f;
        #pragma unroll
        for (int kc = 0; kc < 8; ++kc) {
            int t0 = 2 * kc, t1 = 2 * kc + 1;
            float2 bbA = __ldg(reinterpret_cast<const float2*>(b1 + 8 * t0 + 2 * tq));
            float2 bbB = __ldg(reinterpret_cast<const float2*>(b1 + 8 * t1 + 2 * tq));
            uint32_t ha[4];
            ha[0] = packh2(fmaxf(acc1[t0][0] + bbA.x, 0.f),
                           fmaxf(acc1[t0][1] + bbA.y, 0.f));
            ha[1] = packh2(fmaxf(acc1[t0][2] + bbA.x, 0.f),
                           fmaxf(acc1[t0][3] + bbA.y, 0.f));
            ha[2] = packh2(fmaxf(acc1[t1][0] + bbB.x, 0.f),
                           fmaxf(acc1[t1][1] + bbB.y, 0.f));
            ha[3] = packh2(fmaxf(acc1[t1][2] + bbB.x, 0.f),
                           fmaxf(acc1[t1][3] + bbB.y, 0.f));
            #pragma unroll
            for (int t = 0; t < 16; ++t) {
                int n = 8 * t + gid;
                uint32_t b0 = h2bits(*reinterpret_cast<const __half2*>(
                    &sW2[n * WSTRIDE + kc * 16 + 2 * tq]));
                uint32_t b1v = h2bits(*reinterpret_cast<const __half2*>(
                    &sW2[n * WSTRIDE + kc * 16 + 8 + 2 * tq]));
                mma16816(acc2[t], ha, b0, b1v);
            }
        }

        size_t r0 = (size_t)(mt * 16 + gid) * DD;
        size_t r1 = r0 + (size_t)8 * DD;
        #pragma unroll
        for (int t = 0; t < 16; ++t) {
            int n0 = 8 * t + 2 * tq;
            float2 bb = __ldg(reinterpret_cast<const float2*>(b2 + n0));
            *reinterpret_cast<float2*>(out + r0 + n0) =
                make_float2(acc2[t][0] + bb.x, acc2[t][1] + bb.y);
            *reinterpret_cast<float2*>(out + r1 + n0) =
                make_float2(acc2[t][2] + bb.x, acc2[t][3] + bb.y);
        }
    }
}

// ---------- eh passthrough (stream B) ----------
__global__ void copy_eh_kernel(const float* __restrict__ eh, float* __restrict__ out) {
    int idx = blockIdx.x * blockDim.x + threadIdx.x;
    const int total4 = EE * 16 / 4;
    if (idx < total4)
        reinterpret_cast<float4*>(out)[idx] =
            __ldg(reinterpret_cast<const float4*>(eh) + idx);
}

extern "C" void kernel_launch(void* const* d_in, const int* in_sizes, int n_in,
                              void* d_out, int out_size) {
    const float* nh = nullptr; const float* eh = nullptr; const void* ei = nullptr;
    const float* Wp[2] = {nullptr, nullptr}; const float* bp[2] = {nullptr, nullptr};
    int nw = 0, nb = 0;
    for (int i = 0; i < n_in; ++i) {
        int s = in_sizes[i];
        if (s == NN * DD)            nh = (const float*)d_in[i];
        else if (s == EE * 16)       eh = (const float*)d_in[i];
        else if (s == 2 * EE)        ei = d_in[i];
        else if (s == DD * DD) { if (nw < 2) Wp[nw++] = (const float*)d_in[i]; }
        else if (s == DD)      { if (nb < 2) bp[nb++] = (const float*)d_in[i]; }
    }
    float* out = (float*)d_out;

    // Lazy one-time setup (first call is uncaptured; reused inside capture).
    static cudaStream_t sB = nullptr;
    static cudaEvent_t evFork = nullptr, evNh = nullptr, evEh = nullptr;
    static bool attrSet = false;
    if (!sB) {
        cudaStreamCreateWithFlags(&sB, cudaStreamNonBlocking);
        cudaEventCreateWithFlags(&evFork, cudaEventDisableTiming);
        cudaEventCreateWithFlags(&evNh,   cudaEventDisableTiming);
        cudaEventCreateWithFlags(&evEh,   cudaEventDisableTiming);
    }
    if (!attrSet) {
        cudaFuncSetAttribute(gemm12_kernel,
                             cudaFuncAttributeMaxDynamicSharedMemorySize, SMEM_GEMM);
        attrSet = true;
    }

    // ---- fork stream B: nh->fp16, eh copy ----
    cudaEventRecord(evFork, 0);
    cudaStreamWaitEvent(sB, evFork, 0);
    nh2h_kernel<<<(NN * 32 + 255) / 256, 256, 0, sB>>>(nh);
    cudaEventRecord(evNh, sB);
    copy_eh_kernel<<<(EE * 16 / 4 + 255) / 256, 256, 0, sB>>>(
        eh, out + (size_t)NN * DD);
    cudaEventRecord(evEh, sB);

    // ---- stream A: one persistent CSR kernel, then aggregate + GEMM ----
    csr_kernel<<<NBLK, 256>>>(ei);
    cudaStreamWaitEvent(0, evNh, 0);
    aggregate_kernel<<<(NN * 32 + 255) / 256, 256>>>();
    gemm12_kernel<<<296, 256, SMEM_GEMM>>>(Wp[0], bp[0], Wp[1], bp[1], out);

    // join stream B
    cudaStreamWaitEvent(0, evEh, 0);
}

// round 13
// speedup vs baseline: 1.0943x; 1.0943x over previous
#include <cuda_runtime.h>
#include <cuda_fp16.h>
#include <cstdint>

// GCN layer on GB300, round-13: R11 split CSR chain (measured faster than
// persistent) + issue-optimized aggregate (pre-scaled fp16 features,
// pairwise fp16 pre-add) + register-chained HMMA GEMM1+2.
//   A: init -> degree -> scan -> fill -> aggregate -> gemm12
//   B: nhs (nh * dis[src] -> fp16, after scan)      C: eh copy

#define NN 100000
#define EE 1600000
#define DD 128
#define MTILES 6250        // 100000/16
#define NBLK 391           // ceil(NN/256)
#define WSTRIDE 136
#define SMEM_GEMM (2 * DD * WSTRIDE * (int)sizeof(__half))   // 69,632B

__device__ __align__(128) int     g_cnt[NN];
__device__ __align__(128) int     g_off[NN];
__device__ __align__(128) int     g_cur[NN];
__device__ __align__(128) unsigned long long g_comb[NBLK];  // scan state
__device__ __align__(128) int     g_esrc[EE];
__device__ __align__(128) float   g_dis[NN];
__device__ __align__(128) __half2 g_nhs[(size_t)NN * 64];  // nh*dis fp16
__device__ __align__(128) __half2 g_xh [(size_t)NN * 64];  // agg fp16
__device__ unsigned g_odd_or;   // 0 => edge_index is int64 (zero high words)

// ---------- helpers ----------
__device__ __forceinline__ int edge_idx(const void* ei, int table, int e, bool is64) {
    if (is64) return (int)((const long long*)ei)[(size_t)table * EE + e];
    return ((const int*)ei)[(size_t)table * EE + e];
}
__device__ __forceinline__ uint32_t h2bits(__half2 h) {
    return *reinterpret_cast<uint32_t*>(&h);
}
__device__ __forceinline__ uint32_t packh2(float a, float b) {
    __half2 h = __floats2half2_rn(a, b);
    return *reinterpret_cast<uint32_t*>(&h);
}
__device__ __forceinline__ void mma16816(float c[4], const uint32_t a[4],
                                         uint32_t b0, uint32_t b1) {
    asm volatile(
        "mma.sync.aligned.m16n8k16.row.col.f32.f16.f16.f32 "
        "{%0,%1,%2,%3}, {%4,%5,%6,%7}, {%8,%9}, {%0,%1,%2,%3};"
        : "+f"(c[0]), "+f"(c[1]), "+f"(c[2]), "+f"(c[3])
        : "r"(a[0]), "r"(a[1]), "r"(a[2]), "r"(a[3]), "r"(b0), "r"(b1));
}

// ---------- init: zero counters + scan state, block 0 detects idx dtype ----
__global__ void init_kernel(const unsigned* __restrict__ ei_words) {
    int i = blockIdx.x * 256 + threadIdx.x;
    if (i < NN) g_cnt[i] = 0;
    if (i < NBLK) g_comb[i] = 0ull;
    if (blockIdx.x == 0) {
        __shared__ unsigned sred[256];
        unsigned v = 0;
        #pragma unroll
        for (int j = 0; j < 16; ++j)
            v |= ei_words[2 * (threadIdx.x + 256 * j) + 1];
        sred[threadIdx.x] = v;
        __syncthreads();
        #pragma unroll
        for (int o = 128; o > 0; o >>= 1) {
            if (threadIdx.x < o) sred[threadIdx.x] |= sred[threadIdx.x + o];
            __syncthreads();
        }
        if (threadIdx.x == 0) g_odd_or = sred[0];
    }
}

// ---------- degree histogram ----------
__global__ void degree_kernel(const void* __restrict__ ei) {
    int e = blockIdx.x * blockDim.x + threadIdx.x;
    if (e >= EE) return;
    bool is64 = (g_odd_or == 0u);
    unsigned dst = (unsigned)edge_idx(ei, 1, e, is64);
    if (dst < NN) atomicAdd(&g_cnt[dst], 1);
}

// ---------- single-pass scan (decoupled lookback) ----------
__global__ void __launch_bounds__(256) scan_kernel() {
    __shared__ int s[256];
    __shared__ int sprefix;
    const int tid = threadIdx.x, b = blockIdx.x;
    int i = b * 256 + tid;
    int v = (i < NN) ? g_cnt[i] : 0;
    s[tid] = v;
    __syncthreads();
    #pragma unroll
    for (int o = 1; o < 256; o <<= 1) {
        int x = (tid >= o) ? s[tid - o] : 0;
        __syncthreads();
        s[tid] += x;
        __syncthreads();
    }
    int agg = s[255];
    if (tid == 0) {
        if (b == 0) {
            sprefix = 0;
            atomicExch(&g_comb[0], (2ull << 32) | (unsigned)agg);
        } else {
            atomicExch(&g_comb[b], (1ull << 32) | (unsigned)agg);
        }
    }
    if (b > 0 && tid < 32) {
        const int lane = tid;
        int prefix = 0;
        int base = b - 1;
        while (true) {
            int idx = base - lane;
            unsigned long long c;
            unsigned st;
            do {
                c = (idx >= 0) ? atomicAdd(&g_comb[idx], 0ull) : (2ull << 32);
                st = (unsigned)(c >> 32);
            } while (__any_sync(0xffffffffu, st == 0));
            int val = (int)(c & 0xffffffffu);
            unsigned m2 = __ballot_sync(0xffffffffu, st == 2);
            if (m2) {
                int firstp = __ffs(m2) - 1;
                int contrib = (lane <= firstp) ? val : 0;
                prefix += __reduce_add_sync(0xffffffffu, contrib);
                break;
            }
            prefix += __reduce_add_sync(0xffffffffu, val);
            base -= 32;
        }
        if (lane == 0) {
            atomicExch(&g_comb[b], (2ull << 32) | (unsigned)(prefix + agg));
            sprefix = prefix;
        }
    }
    __syncthreads();
    if (i < NN) {
        int excl = sprefix + s[tid] - v;
        g_off[i] = excl;
        g_cur[i] = excl;
        g_dis[i] = (v > 0) ? rsqrtf((float)v) : 0.f;
    }
}

// ---------- bucket fill ----------
__global__ void fill_kernel(const void* __restrict__ ei) {
    int e = blockIdx.x * blockDim.x + threadIdx.x;
    if (e >= EE) return;
    bool is64 = (g_odd_or == 0u);
    int src = edge_idx(ei, 0, e, is64);
    int dst = edge_idx(ei, 1, e, is64);
    if ((unsigned)src >= NN || (unsigned)dst >= NN) return;
    int pos = atomicAdd(&g_cur[dst], 1);
    g_esrc[pos] = src;
}

// ---------- nhs: g_nhs[i] = fp16(nh[i] * dis[row]) (stream B, after scan) --
__global__ void nhs_kernel(const float* __restrict__ nh) {
    int idx = blockIdx.x * blockDim.x + threadIdx.x;
    if (idx < NN * 32) {
        int row = idx >> 5;
        float d = __ldg(&g_dis[row]);
        float4 v = __ldg(reinterpret_cast<const float4*>(nh) + idx);
        g_nhs[2 * idx]     = __floats2half2_rn(v.x * d, v.y * d);
        g_nhs[2 * idx + 1] = __floats2half2_rn(v.z * d, v.w * d);
    }
}

// ---------- aggregate: warp per node, pairwise fp16 pre-add ----------
// g_xh[d] = fp16( (sum_e g_nhs[src_e]) * dis[d] ). Two edges per step:
// rows added in fp16 (hadd2), pair converted once, fp32 accumulate.
__global__ void aggregate_kernel() {
    int w = (blockIdx.x * blockDim.x + threadIdx.x) >> 5;
    int lane = threadIdx.x & 31;
    if (w >= NN) return;
    int off = g_off[w], len = g_cnt[w];
    float4 acc = make_float4(0.f, 0.f, 0.f, 0.f);
    const float2* NHS = reinterpret_cast<const float2*>(g_nhs);
    for (int b = 0; b < len; b += 32) {
        int n = min(32, len - b);
        int src = (lane < n) ? __ldg(&g_esrc[off + b + lane]) : 0;
        int i = 0;
        #pragma unroll 4
        for (; i + 2 <= n; i += 2) {
            int s0 = __shfl_sync(0xffffffffu, src, i);
            int s1 = __shfl_sync(0xffffffffu, src, i + 1);
            float2 r0 = __ldg(NHS + (size_t)s0 * 32 + lane);
            float2 r1 = __ldg(NHS + (size_t)s1 * 32 + lane);
            __half2 p0 = __hadd2(*reinterpret_cast<__half2*>(&r0.x),
                                 *reinterpret_cast<__half2*>(&r1.x));
            __half2 p1 = __hadd2(*reinterpret_cast<__half2*>(&r0.y),
                                 *reinterpret_cast<__half2*>(&r1.y));
            float2 f0 = __half22float2(p0), f1 = __half22float2(p1);
            acc.x += f0.x; acc.y += f0.y; acc.z += f1.x; acc.w += f1.y;
        }
        if (i < n) {
            int s0 = __shfl_sync(0xffffffffu, src, i);
            float2 r0 = __ldg(NHS + (size_t)s0 * 32 + lane);
            float2 f0 = __half22float2(*reinterpret_cast<__half2*>(&r0.x));
            float2 f1 = __half22float2(*reinterpret_cast<__half2*>(&r0.y));
            acc.x += f0.x; acc.y += f0.y; acc.z += f1.x; acc.w += f1.y;
        }
    }
    float dd = g_dis[w];
    g_xh[(size_t)w * 64 + lane * 2]     = __floats2half2_rn(acc.x * dd, acc.y * dd);
    g_xh[(size_t)w * 64 + lane * 2 + 1] = __floats2half2_rn(acc.z * dd, acc.w * dd);
}

// ---------- fused GEMM1+GEMM2, register-chained HMMA ----------
__global__ void __launch_bounds__(256) gemm12_kernel(
    const float* __restrict__ W1, const float* __restrict__ b1,
    const float* __restrict__ W2, const float* __restrict__ b2,
    float* __restrict__ out) {
    extern __shared__ __half sW[];
    __half* sW1 = sW;
    __half* sW2 = sW + DD * WSTRIDE;
    const int tid = threadIdx.x, lane = tid & 31, warp = tid >> 5;
    const int gid = lane >> 2, tq = lane & 3;

    for (int idx = tid; idx < DD * DD; idx += 256) {
        int k = idx >> 7, n = idx & 127;
        sW1[n * WSTRIDE + k] = __float2half(W1[idx]);
        sW2[n * WSTRIDE + k] = __float2half(W2[idx]);
    }
    __syncthreads();

    for (int mt = blockIdx.x * 8 + warp; mt < MTILES; mt += gridDim.x * 8) {
        const __half2* X0 = g_xh + (size_t)(mt * 16 + gid) * 64;
        const __half2* X1 = X0 + 8 * 64;

        float acc1[16][4];
        #pragma unroll
        for (int t = 0; t < 16; ++t)
            acc1[t][0] = acc1[t][1] = acc1[t][2] = acc1[t][3] = 0.f;
        #pragma unroll
        for (int kc = 0; kc < 8; ++kc) {
            uint32_t a[4];
            a[0] = h2bits(__ldg(X0 + kc * 8 + tq));
            a[1] = h2bits(__ldg(X1 + kc * 8 + tq));
            a[2] = h2bits(__ldg(X0 + kc * 8 + 4 + tq));
            a[3] = h2bits(__ldg(X1 + kc * 8 + 4 + tq));
            #pragma unroll
            for (int t = 0; t < 16; ++t) {
                int n = 8 * t + gid;
                uint32_t b0 = h2bits(*reinterpret_cast<const __half2*>(
                    &sW1[n * WSTRIDE + kc * 16 + 2 * tq]));
                uint32_t b1v = h2bits(*reinterpret_cast<const __half2*>(
                    &sW1[n * WSTRIDE + kc * 16 + 8 + 2 * tq]));
                mma16816(acc1[t], a, b0, b1v);
            }
        }

        float acc2[16][4];
        #pragma unroll
        for (int t = 0; t < 16; ++t)
            acc2[t][0] = acc2[t][1] = acc2[t][2] = acc2[t][3] = 0.f;
        #pragma unroll
        for (int kc = 0; kc < 8; ++kc) {
            int t0 = 2 * kc, t1 = 2 * kc + 1;
            float2 bbA = __ldg(reinterpret_cast<const float2*>(b1 + 8 * t0 + 2 * tq));
            float2 bbB = __ldg(reinterpret_cast<const float2*>(b1 + 8 * t1 + 2 * tq));
            uint32_t ha[4];
            ha[0] = packh2(fmaxf(acc1[t0][0] + bbA.x, 0.f),
                           fmaxf(acc1[t0][1] + bbA.y, 0.f));
            ha[1] = packh2(fmaxf(acc1[t0][2] + bbA.x, 0.f),
                           fmaxf(acc1[t0][3] + bbA.y, 0.f));
            ha[2] = packh2(fmaxf(acc1[t1][0] + bbB.x, 0.f),
                           fmaxf(acc1[t1][1] + bbB.y, 0.f));
            ha[3] = packh2(fmaxf(acc1[t1][2] + bbB.x, 0.f),
                           fmaxf(acc1[t1][3] + bbB.y, 0.f));
            #pragma unroll
            for (int t = 0; t < 16; ++t) {
                int n = 8 * t + gid;
                uint32_t b0 = h2bits(*reinterpret_cast<const __half2*>(
                    &sW2[n * WSTRIDE + kc * 16 + 2 * tq]));
                uint32_t b1v = h2bits(*reinterpret_cast<const __half2*>(
                    &sW2[n * WSTRIDE + kc * 16 + 8 + 2 * tq]));
                mma16816(acc2[t], ha, b0, b1v);
            }
        }

        size_t r0 = (size_t)(mt * 16 + gid) * DD;
        size_t r1 = r0 + (size_t)8 * DD;
        #pragma unroll
        for (int t = 0; t < 16; ++t) {
            int n0 = 8 * t + 2 * tq;
            float2 bb = __ldg(reinterpret_cast<const float2*>(b2 + n0));
            *reinterpret_cast<float2*>(out + r0 + n0) =
                make_float2(acc2[t][0] + bb.x, acc2[t][1] + bb.y);
            *reinterpret_cast<float2*>(out + r1 + n0) =
                make_float2(acc2[t][2] + bb.x, acc2[t][3] + bb.y);
        }
    }
}

// ---------- eh passthrough (stream C) ----------
__global__ void copy_eh_kernel(const float* __restrict__ eh, float* __restrict__ out) {
    int idx = blockIdx.x * blockDim.x + threadIdx.x;
    const int total4 = EE * 16 / 4;
    if (idx < total4)
        reinterpret_cast<float4*>(out)[idx] =
            __ldg(reinterpret_cast<const float4*>(eh) + idx);
}

extern "C" void kernel_launch(void* const* d_in, const int* in_sizes, int n_in,
                              void* d_out, int out_size) {
    const float* nh = nullptr; const float* eh = nullptr; const void* ei = nullptr;
    const float* Wp[2] = {nullptr, nullptr}; const float* bp[2] = {nullptr, nullptr};
    int nw = 0, nb = 0;
    for (int i = 0; i < n_in; ++i) {
        int s = in_sizes[i];
        if (s == NN * DD)            nh = (const float*)d_in[i];
        else if (s == EE * 16)       eh = (const float*)d_in[i];
        else if (s == 2 * EE)        ei = d_in[i];
        else if (s == DD * DD) { if (nw < 2) Wp[nw++] = (const float*)d_in[i]; }
        else if (s == DD)      { if (nb < 2) bp[nb++] = (const float*)d_in[i]; }
    }
    float* out = (float*)d_out;

    // Lazy one-time setup (first call is uncaptured; reused inside capture).
    static cudaStream_t sB = nullptr, sC = nullptr;
    static cudaEvent_t evFork = nullptr, evScan = nullptr,
                       evNhs = nullptr, evEh = nullptr;
    static bool attrSet = false;
    if (!sB) {
        cudaStreamCreateWithFlags(&sB, cudaStreamNonBlocking);
        cudaStreamCreateWithFlags(&sC, cudaStreamNonBlocking);
        cudaEventCreateWithFlags(&evFork, cudaEventDisableTiming);
        cudaEventCreateWithFlags(&evScan, cudaEventDisableTiming);
        cudaEventCreateWithFlags(&evNhs,  cudaEventDisableTiming);
        cudaEventCreateWithFlags(&evEh,   cudaEventDisableTiming);
    }
    if (!attrSet) {
        cudaFuncSetAttribute(gemm12_kernel,
                             cudaFuncAttributeMaxDynamicSharedMemorySize, SMEM_GEMM);
        attrSet = true;
    }

    // ---- stream C: eh passthrough (fully independent) ----
    cudaEventRecord(evFork, 0);
    cudaStreamWaitEvent(sC, evFork, 0);
    copy_eh_kernel<<<(EE * 16 / 4 + 255) / 256, 256, 0, sC>>>(
        eh, out + (size_t)NN * DD);
    cudaEventRecord(evEh, sC);

    // ---- stream A: CSR chain ----
    init_kernel<<<NBLK, 256>>>((const unsigned*)ei);
    degree_kernel<<<(EE + 255) / 256, 256>>>(ei);
    scan_kernel<<<NBLK, 256>>>();
    cudaEventRecord(evScan, 0);
    fill_kernel<<<(EE + 255) / 256, 256>>>(ei);

    // ---- stream B: pre-scaled fp16 features (needs g_dis; overlaps fill) --
    cudaStreamWaitEvent(sB, evScan, 0);
    nhs_kernel<<<(NN * 32 + 255) / 256, 256, 0, sB>>>(nh);
    cudaEventRecord(evNhs, sB);

    // ---- aggregate + fused GEMM ----
    cudaStreamWaitEvent(0, evNhs, 0);
    aggregate_kernel<<<(NN * 32 + 255) / 256, 256>>>();
    gemm12_kernel<<<296, 256, SMEM_GEMM>>>(Wp[0], bp[0], Wp[1], bp[1], out);

    // join stream C
    cudaStreamWaitEvent(0, evEh, 0);
}